// round 7
// baseline (speedup 1.0000x reference)
#include <cuda_runtime.h>
#include <cuda_bf16.h>
#include <cstdint>

// HarmonicLowering: x (8,32,256,512) f32 -> out (8,128,256,512) f32
//   out[b, k*32+c, i, t] = w*x[b,c,idx,t] + (1-w)*x[b,c,idx1,t]
//   prod=i*(k+1), idx=prod>>2, rem=prod&3, w=1-rem/4  (idx1=idx+1, never
//   needs clamping when rem!=0: max idx1 = 192 < 256)
//
// R6: software-pipelined warp over 8 consecutive i rows (same bc,k ->
// warp-uniform control). Row n+1's g0 loads issue before row n's blend/store,
// so each warp always has loads outstanding -> continuous DRAM issue.
// 4096 long-lived CTAs reduce launch/drain churn. Grid ordering keeps each
// (b,c) input plane L2-resident; streaming stores for write-once output.

static constexpr int BATCH = 8;
static constexpr int C     = 32;
static constexpr int FREQ  = 256;
static constexpr int TIME  = 512;
static constexpr int T4    = TIME / 4;      // 128 float4 per row
static constexpr int K     = 4;

static constexpr int ROWS_PER_WARP   = 8;
static constexpr int WARPS_PER_BLOCK = 8;
static constexpr int THREADS         = 256;
static constexpr int ROWS_TOTAL      = BATCH * C * K * FREQ;              // 262144
static constexpr int NBLOCKS = ROWS_TOTAL / (ROWS_PER_WARP * WARPS_PER_BLOCK); // 4096

__global__ __launch_bounds__(THREADS) void harmonic_lowering_kernel(
    const float4* __restrict__ in, float4* __restrict__ out)
{
    const int lane = threadIdx.x & 31;
    const int wid  = blockIdx.x * WARPS_PER_BLOCK + (threadIdx.x >> 5);
    const int row0 = wid * ROWS_PER_WARP;          // 8-aligned -> same bc,k

    const int i0 = row0 & (FREQ - 1);
    int r = row0 >> 8;
    const int k = r & (K - 1);
    r >>= 2;                                       // bc = b*C + c

    const float4* base = in + ((unsigned)r << 15); // bc * FREQ * T4
    const int b = r >> 5, c = r & (C - 1);
    float4* po = out + (((((unsigned)b * (K * C) + (unsigned)k * C + c) << 8)
                         + i0) << 7) + lane;

    const int step = k + 1;
    int prod = i0 * step;

    // Prologue: first row's primary loads
    float4 cur[4];
    {
        const float4* p = base + ((prod >> 2) << 7) + lane;
#pragma unroll
        for (int j = 0; j < 4; j++) cur[j] = __ldg(p + j * 32);
    }

#pragma unroll
    for (int rr = 0; rr < ROWS_PER_WARP; rr++) {
        const int rem   = prod & 3;
        const int nprod = prod + step;

        // Prefetch next row's primary loads before this row's blend/store
        float4 nxt[4];
        if (rr < ROWS_PER_WARP - 1) {
            const float4* pn = base + ((nprod >> 2) << 7) + lane;
#pragma unroll
            for (int j = 0; j < 4; j++) nxt[j] = __ldg(pn + j * 32);
        }

        float4* prow = po + rr * T4;
        if (rem) {                                 // warp-uniform branch
            const float4* p1 = base + (((prod >> 2) + 1) << 7) + lane;
            float4 g1[4];
#pragma unroll
            for (int j = 0; j < 4; j++) g1[j] = __ldg(p1 + j * 32);
            const float w  = 1.0f - 0.25f * (float)rem;
            const float w1 = 1.0f - w;
#pragma unroll
            for (int j = 0; j < 4; j++) {
                float4 o;
                o.x = w * cur[j].x + w1 * g1[j].x;
                o.y = w * cur[j].y + w1 * g1[j].y;
                o.z = w * cur[j].z + w1 * g1[j].z;
                o.w = w * cur[j].w + w1 * g1[j].w;
                __stcs(prow + j * 32, o);
            }
        } else {                                   // w == 1: pure copy
#pragma unroll
            for (int j = 0; j < 4; j++) __stcs(prow + j * 32, cur[j]);
        }

        if (rr < ROWS_PER_WARP - 1) {
#pragma unroll
            for (int j = 0; j < 4; j++) cur[j] = nxt[j];
        }
        prod = nprod;
    }
}

extern "C" void kernel_launch(void* const* d_in, const int* in_sizes, int n_in,
                              void* d_out, int out_size)
{
    const float4* in = (const float4*)d_in[0];
    float4* out = (float4*)d_out;
    harmonic_lowering_kernel<<<NBLOCKS, THREADS>>>(in, out);
}

// round 8
// speedup vs baseline: 1.0571x; 1.0571x over previous
#include <cuda_runtime.h>
#include <cuda_bf16.h>
#include <cstdint>

// HarmonicLowering: x (8,32,256,512) f32 -> out (8,128,256,512) f32
//   out[b, k*32+c, i, t] = w*x[b,c,idx,t] + (1-w)*x[b,c,idx1,t]
//   prod=i*(k+1), idx=prod>>2, rem=prod&3, w=1-rem/4
//   (when rem!=0, idx+1 <= 192 < 256: no clamp needed)
//
// R7: warp-per-row (i,k,bc warp-uniform) like R4, but the 128-float4 row is
// processed in TWO halves of 2 float4/lane. Live load data drops 8->4 float4
// (~30 regs vs 38) -> 8 CTAs/SM theoretical (64 warps) while per-thread MLP
// stays 2-4 continuously. High-occupancy + moderate-MLP quadrant.
// Grid ordering keeps each (b,c) input plane (512 KiB) L2-resident;
// streaming stores for the write-once output.

static constexpr int BATCH = 8;
static constexpr int C     = 32;
static constexpr int FREQ  = 256;
static constexpr int TIME  = 512;
static constexpr int T4    = TIME / 4;      // 128 float4 per row
static constexpr int K     = 4;

static constexpr int THREADS = 256;         // 8 warps = 8 rows per block
static constexpr int ROWS_TOTAL = BATCH * C * K * FREQ;   // 262144
static constexpr int NBLOCKS = ROWS_TOTAL / 8;            // 32768

__global__ __launch_bounds__(THREADS, 8) void harmonic_lowering_kernel(
    const float4* __restrict__ in, float4* __restrict__ out)
{
    const int lane = threadIdx.x & 31;
    const int wrow = blockIdx.x * 8 + (threadIdx.x >> 5);  // global row id

    // wrow = ((bc)*K + k)*FREQ + i
    int i = wrow & (FREQ - 1);
    int r = wrow >> 8;
    const int k = r & (K - 1);
    r >>= 2;                               // bc = b*C + c, in [0,256)

    const int prod = i * (k + 1);
    const int idx  = prod >> 2;
    const int rem  = prod & 3;

    const float4* base = in + ((unsigned)r << 15);          // bc * 32768
    const float4* p0 = base + (idx << 7) + lane;
    const float4* p1 = p0 + T4;                             // row idx+1

    const int b = r >> 5, c = r & (C - 1);
    float4* po = out + (((((unsigned)b * (K * C) + (unsigned)k * C + c) << 8)
                         + i) << 7) + lane;

    const float w  = 1.0f - 0.25f * (float)rem;
    const float w1 = 0.25f * (float)rem;

    if (rem) {                             // warp-uniform branch
#pragma unroll
        for (int h = 0; h < 2; h++) {      // two halves of the row
            const int o0 = h * 64, o1 = h * 64 + 32;
            float4 a0 = __ldg(p0 + o0);
            float4 a1 = __ldg(p0 + o1);
            float4 c0 = __ldg(p1 + o0);
            float4 c1 = __ldg(p1 + o1);
            float4 o;
            o.x = w * a0.x + w1 * c0.x;
            o.y = w * a0.y + w1 * c0.y;
            o.z = w * a0.z + w1 * c0.z;
            o.w = w * a0.w + w1 * c0.w;
            __stcs(po + o0, o);
            o.x = w * a1.x + w1 * c1.x;
            o.y = w * a1.y + w1 * c1.y;
            o.z = w * a1.z + w1 * c1.z;
            o.w = w * a1.w + w1 * c1.w;
            __stcs(po + o1, o);
        }
    } else {                               // w == 1: pure row copy
#pragma unroll
        for (int h = 0; h < 2; h++) {
            const int o0 = h * 64, o1 = h * 64 + 32;
            float4 a0 = __ldg(p0 + o0);
            float4 a1 = __ldg(p0 + o1);
            __stcs(po + o0, a0);
            __stcs(po + o1, a1);
        }
    }
}

extern "C" void kernel_launch(void* const* d_in, const int* in_sizes, int n_in,
                              void* d_out, int out_size)
{
    const float4* in = (const float4*)d_in[0];
    float4* out = (float4*)d_out;
    harmonic_lowering_kernel<<<NBLOCKS, THREADS>>>(in, out);
}